// round 15
// baseline (speedup 1.0000x reference)
#include <cuda_runtime.h>
#include <cuda_bf16.h>
#include <math.h>
#include <stdint.h>

#define N_NODES 50000
#define N_EDGES 800000
#define DIN     256
#define H       384
#define NLAYERS 6
#define NCLS    2
#define EPSV    1e-5f

typedef __nv_bfloat16 bf16;

// ---------------- fp32 scratch ----------------
__device__ float g_h   [(size_t)N_NODES * H];
__device__ float g_tmp [(size_t)N_NODES * H];
__device__ float g_t1f [(size_t)N_NODES * H];
__device__ float g_stats[2 * H];
__device__ float g_bna [H];
__device__ float g_bnc [H];
__device__ float g_invcnt[N_NODES];
__device__ int   g_deg   [N_NODES];
__device__ int   g_colptr[N_NODES + 1];
__device__ int   g_cursor[N_NODES];
__device__ int   g_src   [N_EDGES];

// ---------------- bf16 split scratch ----------------
#define NH ((size_t)N_NODES * H)
static const size_t OFF_HSA_H = 0;
static const size_t OFF_HSA_L = 1 * NH;
static const size_t OFF_HSB_H = 2 * NH;
static const size_t OFF_HSB_L = 3 * NH;
static const size_t OFF_AGG_H = 4 * NH;
static const size_t OFF_AGG_L = 5 * NH;
static const size_t OFF_X_H   = 6 * NH;
static const size_t OFF_X_L   = 7 * NH;
static const size_t OFF_T1_H  = 8 * NH;
static const size_t OFF_T1_L  = 9 * NH;
static const size_t SZ_WIN = (size_t)DIN * H;
static const size_t SZ_WL  = (size_t)NLAYERS * H * H;
static const size_t SZ_WSK = (size_t)(NLAYERS / 2) * H * H;
static const size_t SZ_W1  = (size_t)H * (H / 2);
static const size_t SZ_W2  = (size_t)(H / 2) * (H / 4);
static const size_t OFF_WIN_H = 10 * NH;
static const size_t OFF_WIN_L = OFF_WIN_H + SZ_WIN;
static const size_t OFF_WL_H  = OFF_WIN_L + SZ_WIN;
static const size_t OFF_WL_L  = OFF_WL_H + SZ_WL;
static const size_t OFF_WR_H  = OFF_WL_L + SZ_WL;
static const size_t OFF_WR_L  = OFF_WR_H + SZ_WL;
static const size_t OFF_WSK_H = OFF_WR_L + SZ_WL;
static const size_t OFF_WSK_L = OFF_WSK_H + SZ_WSK;
static const size_t OFF_W1_H  = OFF_WSK_L + SZ_WSK;
static const size_t OFF_W1_L  = OFF_W1_H + SZ_W1;
static const size_t OFF_W2_H  = OFF_W1_L + SZ_W1;
static const size_t OFF_W2_L  = OFF_W2_H + SZ_W2;
static const size_t BF_TOTAL  = OFF_W2_L + SZ_W2;

__device__ bf16 g_bf[BF_TOTAL];

// ---------------- CSR build ----------------
__global__ void hist_kernel(const int* __restrict__ col) {
    int i = blockIdx.x * blockDim.x + threadIdx.x;
    if (i < N_EDGES) atomicAdd(&g_deg[col[i]], 1);
}

__global__ void scan_kernel() {
    __shared__ int buf[1024];
    int tid = threadIdx.x;
    int offset = 0;
    for (int base = 0; base < N_NODES; base += 1024) {
        int idx = base + tid;
        int v = (idx < N_NODES) ? g_deg[idx] : 0;
        buf[tid] = v;
        __syncthreads();
        for (int s = 1; s < 1024; s <<= 1) {
            int t = (tid >= s) ? buf[tid - s] : 0;
            __syncthreads();
            buf[tid] += t;
            __syncthreads();
        }
        if (idx < N_NODES) g_colptr[idx] = offset + buf[tid] - v;
        int tot = buf[1023];
        __syncthreads();
        offset += tot;
    }
    if (tid == 0) g_colptr[N_NODES] = offset;
}

__global__ void fill_kernel(const int* __restrict__ row, const int* __restrict__ col) {
    int i = blockIdx.x * blockDim.x + threadIdx.x;
    if (i < N_EDGES) {
        int p = atomicAdd(&g_cursor[col[i]], 1);
        g_src[p] = row[i];
    }
}

__global__ void invcnt_kernel() {
    int i = blockIdx.x * blockDim.x + threadIdx.x;
    if (i < N_NODES) g_invcnt[i] = 1.0f / fmaxf((float)g_deg[i], 1.0f);
}

// ---------------- splits ----------------
__global__ void split_kernel(const float* __restrict__ src,
                             bf16* __restrict__ hi, bf16* __restrict__ lo, int n) {
    int i = blockIdx.x * blockDim.x + threadIdx.x;
    if (i < n) {
        float v = src[i];
        bf16 h = __float2bfloat16(v);
        hi[i] = h;
        lo[i] = __float2bfloat16(v - __bfloat162float(h));
    }
}

// ---------------- mean aggregation: unroll-4 edge loop for MLP ----------------
__global__ void agg_kernel(const float* __restrict__ h,
                           bf16* __restrict__ ohi, bf16* __restrict__ olo) {
    int w    = (blockIdx.x * blockDim.x + threadIdx.x) >> 5;
    int lane = threadIdx.x & 31;
    if (w >= N_NODES) return;
    int beg = g_colptr[w], end = g_colptr[w + 1];
    float4 a0 = make_float4(0.f, 0.f, 0.f, 0.f);
    float4 a1 = a0, a2 = a0;

    int e = beg;
    // main: 4 edges per iteration -> 12 independent float4 gathers in flight
    for (; e + 4 <= end; e += 4) {
        const float4* p0 = (const float4*)(h + (size_t)g_src[e]     * H);
        const float4* p1 = (const float4*)(h + (size_t)g_src[e + 1] * H);
        const float4* p2 = (const float4*)(h + (size_t)g_src[e + 2] * H);
        const float4* p3 = (const float4*)(h + (size_t)g_src[e + 3] * H);
        float4 u0 = p0[lane], u1 = p0[lane + 32], u2 = p0[lane + 64];
        float4 v0 = p1[lane], v1 = p1[lane + 32], v2 = p1[lane + 64];
        float4 w0 = p2[lane], w1 = p2[lane + 32], w2 = p2[lane + 64];
        float4 x0 = p3[lane], x1 = p3[lane + 32], x2 = p3[lane + 64];
        a0.x += u0.x + v0.x + w0.x + x0.x;
        a0.y += u0.y + v0.y + w0.y + x0.y;
        a0.z += u0.z + v0.z + w0.z + x0.z;
        a0.w += u0.w + v0.w + w0.w + x0.w;
        a1.x += u1.x + v1.x + w1.x + x1.x;
        a1.y += u1.y + v1.y + w1.y + x1.y;
        a1.z += u1.z + v1.z + w1.z + x1.z;
        a1.w += u1.w + v1.w + w1.w + x1.w;
        a2.x += u2.x + v2.x + w2.x + x2.x;
        a2.y += u2.y + v2.y + w2.y + x2.y;
        a2.z += u2.z + v2.z + w2.z + x2.z;
        a2.w += u2.w + v2.w + w2.w + x2.w;
    }
    // cleanup
    for (; e < end; e++) {
        const float4* hp = (const float4*)(h + (size_t)g_src[e] * H);
        float4 v0 = hp[lane];
        float4 v1 = hp[lane + 32];
        float4 v2 = hp[lane + 64];
        a0.x += v0.x; a0.y += v0.y; a0.z += v0.z; a0.w += v0.w;
        a1.x += v1.x; a1.y += v1.y; a1.z += v1.z; a1.w += v1.w;
        a2.x += v2.x; a2.y += v2.y; a2.z += v2.z; a2.w += v2.w;
    }

    float s = g_invcnt[w];
    float vals[12] = {a0.x*s, a0.y*s, a0.z*s, a0.w*s,
                      a1.x*s, a1.y*s, a1.z*s, a1.w*s,
                      a2.x*s, a2.y*s, a2.z*s, a2.w*s};
    size_t base = (size_t)w * H + lane * 4;
#pragma unroll
    for (int g = 0; g < 3; g++) {
#pragma unroll
        for (int j = 0; j < 4; j++) {
            float v = vals[g * 4 + j];
            bf16 hb = __float2bfloat16(v);
            ohi[base + g * 128 + j] = hb;
            olo[base + g * 128 + j] = __float2bfloat16(v - __bfloat162float(hb));
        }
    }
}

// ---------------- mma helpers ----------------
__device__ __forceinline__ void ldsm_x4(uint32_t* r, const void* p) {
    uint32_t a = (uint32_t)__cvta_generic_to_shared(p);
    asm volatile("ldmatrix.sync.aligned.m8n8.x4.shared.b16 {%0,%1,%2,%3}, [%4];"
                 : "=r"(r[0]), "=r"(r[1]), "=r"(r[2]), "=r"(r[3]) : "r"(a));
}
__device__ __forceinline__ void ldsm_x4t(uint32_t* r, const void* p) {
    uint32_t a = (uint32_t)__cvta_generic_to_shared(p);
    asm volatile("ldmatrix.sync.aligned.m8n8.x4.trans.shared.b16 {%0,%1,%2,%3}, [%4];"
                 : "=r"(r[0]), "=r"(r[1]), "=r"(r[2]), "=r"(r[3]) : "r"(a));
}
__device__ __forceinline__ void mma16816(float* d, const uint32_t* a, const uint32_t* b) {
    asm volatile("mma.sync.aligned.m16n8k16.row.col.f32.bf16.bf16.f32 "
                 "{%0,%1,%2,%3}, {%4,%5,%6,%7}, {%8,%9}, {%0,%1,%2,%3};"
                 : "+f"(d[0]), "+f"(d[1]), "+f"(d[2]), "+f"(d[3])
                 : "r"(a[0]), "r"(a[1]), "r"(a[2]), "r"(a[3]), "r"(b[0]), "r"(b[1]));
}
__device__ __forceinline__ void cpasync16(void* dst, const void* src, bool pred) {
    uint32_t d = (uint32_t)__cvta_generic_to_shared(dst);
    int sz = pred ? 16 : 0;
    asm volatile("cp.async.cg.shared.global [%0], [%1], 16, %2;"
                 :: "r"(d), "l"(src), "r"(sz) : "memory");
}
#define CP_COMMIT() asm volatile("cp.async.commit_group;" ::: "memory")
#define CP_WAIT1()  asm volatile("cp.async.wait_group 1;" ::: "memory")
#define CP_WAIT0()  asm volatile("cp.async.wait_group 0;" ::: "memory")

// ---------------- bf16x3 tensor-core GEMM, 2-stage cp.async pipeline ----------------
// flags: 1=+bias, 2=acc C, 4=relu, 8=fused BN col-stats, 16=skip-BN (v = relu(bn(Cin)) + acc + bias)
static const int A_PITCH = 40;
static const int B_PITCH = 136;
static const int A_ELEMS = 128 * A_PITCH;
static const int B_ELEMS = 32 * B_PITCH;
static const int STAGE_ELEMS = 2 * A_ELEMS + 2 * B_ELEMS;   // 18944 bf16 = 37888 B
static const int SMEM_DYN = 2 * STAGE_ELEMS * 2;            // 75776 B

__global__ void __launch_bounds__(256) gemm_mma_kernel(
    const bf16* __restrict__ a1h, const bf16* __restrict__ a1l,
    const bf16* __restrict__ b1h, const bf16* __restrict__ b1l, int K1,
    const bf16* __restrict__ a2h, const bf16* __restrict__ a2l,
    const bf16* __restrict__ b2h, const bf16* __restrict__ b2l, int K2,
    const float* __restrict__ bias,
    const float* __restrict__ Cin, float* __restrict__ Cout,
    bf16* __restrict__ ohi, bf16* __restrict__ olo,
    int M, int Nc, int flags)
{
    extern __shared__ bf16 sm[];

    const int tid  = threadIdx.x;
    const int lane = tid & 31;
    const int wid  = tid >> 5;
    const int wm   = (wid >> 2) * 64;
    const int wn   = (wid & 3) * 32;
    const int m0   = blockIdx.y * 128;
    const int n0   = blockIdx.x * 128;

    const int nch1 = K1 >> 5;
    const int nch2 = (a2h != nullptr) ? (K2 >> 5) : 0;
    const int NCH  = nch1 + nch2;

    float acc[4][4][4];
#pragma unroll
    for (int i = 0; i < 4; i++)
#pragma unroll
        for (int j = 0; j < 4; j++)
#pragma unroll
            for (int k = 0; k < 4; k++) acc[i][j][k] = 0.f;

    auto load_stage = [&](int buf, int c) {
        const bf16 *ah, *al, *bh, *bl; int K, kk;
        if (c < nch1) { ah = a1h; al = a1l; bh = b1h; bl = b1l; K = K1; kk = c * 32; }
        else          { ah = a2h; al = a2l; bh = b2h; bl = b2l; K = K2; kk = (c - nch1) * 32; }
        bf16* AhS = sm + buf * STAGE_ELEMS;
        bf16* AlS = AhS + A_ELEMS;
        bf16* BhS = AlS + A_ELEMS;
        bf16* BlS = BhS + B_ELEMS;
#pragma unroll
        for (int t = 0; t < 2; t++) {
            int idx = tid + t * 256;
            int row = idx >> 2, cg = idx & 3;
            int gr = m0 + row;
            bool ok = gr < M;
            size_t so = (size_t)gr * K + kk + cg * 8;
            int doff = row * A_PITCH + cg * 8;
            cpasync16(AhS + doff, ah + (ok ? so : 0), ok);
            cpasync16(AlS + doff, al + (ok ? so : 0), ok);
        }
#pragma unroll
        for (int t = 0; t < 2; t++) {
            int idx = tid + t * 256;
            int row = idx >> 4, cg = idx & 15;
            int gc = n0 + cg * 8;
            bool ok = gc < Nc;
            size_t so = (size_t)(kk + row) * Nc + (ok ? gc : 0);
            int doff = row * B_PITCH + cg * 8;
            cpasync16(BhS + doff, bh + so, ok);
            cpasync16(BlS + doff, bl + so, ok);
        }
    };

    auto compute_stage = [&](int buf) {
        const bf16* AhS = sm + buf * STAGE_ELEMS;
        const bf16* AlS = AhS + A_ELEMS;
        const bf16* BhS = AlS + A_ELEMS;
#pragma unroll
        for (int ks = 0; ks < 2; ks++) {
            uint32_t bfh[8], bfl[8], af[4][4];
#pragma unroll
            for (int ni2 = 0; ni2 < 2; ni2++) {
                const bf16* bb = BhS + (ks * 16 + (lane & 15)) * B_PITCH
                                     + wn + ni2 * 16 + ((lane >> 4) << 3);
                ldsm_x4t(&bfh[ni2 * 4], bb);
                ldsm_x4t(&bfl[ni2 * 4], bb + B_ELEMS);
            }
#pragma unroll
            for (int mi = 0; mi < 4; mi++)
                ldsm_x4(af[mi], AhS + (wm + mi * 16 + (lane & 15)) * A_PITCH
                                   + ks * 16 + (lane >> 4) * 8);
#pragma unroll
            for (int mi = 0; mi < 4; mi++)
#pragma unroll
                for (int ni = 0; ni < 4; ni++)
                    mma16816(acc[mi][ni], af[mi], &bfh[ni * 2]);
#pragma unroll
            for (int mi = 0; mi < 4; mi++)
#pragma unroll
                for (int ni = 0; ni < 4; ni++)
                    mma16816(acc[mi][ni], af[mi], &bfl[ni * 2]);
#pragma unroll
            for (int mi = 0; mi < 4; mi++)
                ldsm_x4(af[mi], AlS + (wm + mi * 16 + (lane & 15)) * A_PITCH
                                   + ks * 16 + (lane >> 4) * 8);
#pragma unroll
            for (int mi = 0; mi < 4; mi++)
#pragma unroll
                for (int ni = 0; ni < 4; ni++)
                    mma16816(acc[mi][ni], af[mi], &bfh[ni * 2]);
        }
    };

    // ---- 2-stage double buffer ----
    load_stage(0, 0);
    CP_COMMIT();
    for (int c = 0; c < NCH; c++) {
        if (c + 1 < NCH) load_stage((c + 1) & 1, c + 1);
        CP_COMMIT();
        CP_WAIT1();
        __syncthreads();
        compute_stage(c & 1);
        __syncthreads();
    }
    CP_WAIT0();

    // ---- epilogue ----
    float* scol = (float*)sm;
    const bool do_stats = (flags & 8) != 0;
    if (do_stats) {
        if (tid < 256) scol[tid] = 0.f;
        __syncthreads();
    }

    float ls[4][2], ls2[4][2];
    if (do_stats) {
#pragma unroll
        for (int ni = 0; ni < 4; ni++) { ls[ni][0]=ls[ni][1]=ls2[ni][0]=ls2[ni][1]=0.f; }
    }

#pragma unroll
    for (int mi = 0; mi < 4; mi++) {
#pragma unroll
        for (int ni = 0; ni < 4; ni++) {
            int rbase = m0 + wm + mi * 16 + (lane >> 2);
            int cbase = n0 + wn + ni * 8 + (lane & 3) * 2;
#pragma unroll
            for (int half = 0; half < 2; half++) {
                int r = rbase + half * 8;
                if (r < M) {
#pragma unroll
                    for (int j = 0; j < 2; j++) {
                        int c = cbase + j;
                        if (c < Nc) {
                            float v = acc[mi][ni][half * 2 + j];
                            if (flags & 1) v += bias[c];
                            if (flags & 2) v += Cin[(size_t)r * Nc + c];
                            if (flags & 16) {
                                float old = Cin[(size_t)r * Nc + c];
                                v += fmaxf(fmaf(old, g_bna[c], g_bnc[c]), 0.f);
                            }
                            if (flags & 4) v = fmaxf(v, 0.f);
                            Cout[(size_t)r * Nc + c] = v;
                            if (do_stats) {
                                ls [ni][j] += v;
                                ls2[ni][j] = fmaf(v, v, ls2[ni][j]);
                            }
                            if (ohi) {
                                bf16 hv = __float2bfloat16(v);
                                ohi[(size_t)r * Nc + c] = hv;
                                olo[(size_t)r * Nc + c] =
                                    __float2bfloat16(v - __bfloat162float(hv));
                            }
                        }
                    }
                }
            }
        }
    }

    if (do_stats) {
#pragma unroll
        for (int ni = 0; ni < 4; ni++) {
#pragma unroll
            for (int j = 0; j < 2; j++) {
                int cloc = wn + ni * 8 + (lane & 3) * 2 + j;
                atomicAdd(&scol[cloc], ls[ni][j]);
                atomicAdd(&scol[128 + cloc], ls2[ni][j]);
            }
        }
        __syncthreads();
        if (tid < 128) {
            int c = n0 + tid;
            if (c < Nc) {
                atomicAdd(&g_stats[c],     scol[tid]);
                atomicAdd(&g_stats[H + c], scol[128 + tid]);
            }
        }
    }
}

// ---------------- batchnorm ----------------
__global__ void bn_final_kernel(const float* __restrict__ g, const float* __restrict__ b) {
    int c = threadIdx.x;
    if (c < H) {
        float inv = 1.0f / (float)N_NODES;
        float mu  = g_stats[c] * inv;
        float var = g_stats[H + c] * inv - mu * mu;
        float rs  = rsqrtf(var + EPSV);
        float a   = g[c] * rs;
        g_bna[c] = a;
        g_bnc[c] = b[c] - mu * a;
        g_stats[c]     = 0.f;
        g_stats[H + c] = 0.f;
    }
}

__global__ void bn_apply_relu_kernel(float* __restrict__ h,
                                     bf16* __restrict__ ohi, bf16* __restrict__ olo) {
    int i = blockIdx.x * blockDim.x + threadIdx.x;
    const int total = N_NODES * H / 4;
    if (i >= total) return;
    int c4 = i % (H / 4);
    float4 v = ((float4*)h)[i];
    float4 a = ((const float4*)g_bna)[c4];
    float4 c = ((const float4*)g_bnc)[c4];
    v.x = fmaxf(fmaf(v.x, a.x, c.x), 0.f);
    v.y = fmaxf(fmaf(v.y, a.y, c.y), 0.f);
    v.z = fmaxf(fmaf(v.z, a.z, c.z), 0.f);
    v.w = fmaxf(fmaf(v.w, a.w, c.w), 0.f);
    ((float4*)h)[i] = v;
    if (ohi) {
        size_t base = (size_t)i * 4;
        float vv[4] = {v.x, v.y, v.z, v.w};
        bf16 hb[4], lb[4];
#pragma unroll
        for (int j = 0; j < 4; j++) {
            hb[j] = __float2bfloat16(vv[j]);
            lb[j] = __float2bfloat16(vv[j] - __bfloat162float(hb[j]));
        }
        ((__nv_bfloat162*)(ohi + base))[0] = __halves2bfloat162(hb[0], hb[1]);
        ((__nv_bfloat162*)(ohi + base))[1] = __halves2bfloat162(hb[2], hb[3]);
        ((__nv_bfloat162*)(olo + base))[0] = __halves2bfloat162(lb[0], lb[1]);
        ((__nv_bfloat162*)(olo + base))[1] = __halves2bfloat162(lb[2], lb[3]);
    }
}

// ---------------- final tiny GEMM ----------------
__global__ void head3_kernel(const float* __restrict__ t2, const float* __restrict__ W3,
                             const float* __restrict__ b3, float* __restrict__ out) {
    __shared__ float w[96 * 2];
    __shared__ float bb[2];
    if (threadIdx.x < 192) w[threadIdx.x] = W3[threadIdx.x];
    if (threadIdx.x < 2)   bb[threadIdx.x] = b3[threadIdx.x];
    __syncthreads();
    int r = blockIdx.x * blockDim.x + threadIdx.x;
    if (r >= N_NODES) return;
    float a0 = bb[0], a1 = bb[1];
    const float* row = t2 + (size_t)r * 96;
#pragma unroll 8
    for (int k = 0; k < 96; k++) {
        float v = row[k];
        a0 = fmaf(v, w[k * 2],     a0);
        a1 = fmaf(v, w[k * 2 + 1], a1);
    }
    out[r * 2]     = a0;
    out[r * 2 + 1] = a1;
}

// ---------------- host orchestration ----------------
static void run_split(const float* src, bf16* hi, bf16* lo, size_t n) {
    split_kernel<<<(int)((n + 255) / 256), 256>>>(src, hi, lo, (int)n);
}

static void run_gemm(const bf16* a1h, const bf16* a1l, const bf16* b1h, const bf16* b1l, int K1,
                     const bf16* a2h, const bf16* a2l, const bf16* b2h, const bf16* b2l, int K2,
                     const float* bias, const float* Cin, float* Cout, bf16* ohi, bf16* olo,
                     int M, int Nc, int flags) {
    static int attr_set = 0;
    if (!attr_set) {
        cudaFuncSetAttribute(gemm_mma_kernel,
                             cudaFuncAttributeMaxDynamicSharedMemorySize, SMEM_DYN);
        attr_set = 1;
    }
    dim3 grid((Nc + 127) / 128, (M + 127) / 128);
    gemm_mma_kernel<<<grid, 256, SMEM_DYN>>>(a1h, a1l, b1h, b1l, K1,
                                             a2h, a2l, b2h, b2l, K2,
                                             bias, Cin, Cout, ohi, olo, M, Nc, flags);
}

extern "C" void kernel_launch(void* const* d_in, const int* in_sizes, int n_in,
                              void* d_out, int out_size) {
    const float* x     = (const float*)d_in[0];
    const int*   ei    = (const int*)  d_in[1];
    const float* W_in  = (const float*)d_in[2];
    const float* b_in  = (const float*)d_in[3];
    const float* bn0_g = (const float*)d_in[4];
    const float* bn0_b = (const float*)d_in[5];
    const float* Wl    = (const float*)d_in[6];
    const float* bl    = (const float*)d_in[7];
    const float* Wr    = (const float*)d_in[8];
    const float* bn_g  = (const float*)d_in[9];
    const float* bn_b  = (const float*)d_in[10];
    const float* Wskip = (const float*)d_in[11];
    const float* bskip = (const float*)d_in[12];
    const float* W1    = (const float*)d_in[13];
    const float* b1    = (const float*)d_in[14];
    const float* W2    = (const float*)d_in[15];
    const float* b2    = (const float*)d_in[16];
    const float* W3    = (const float*)d_in[17];
    const float* b3    = (const float*)d_in[18];

    float* logits_out = (float*)d_out;
    float* emb_out    = logits_out + (size_t)N_NODES * NCLS;

    float *hf, *tf, *t1f, *stats;
    int *deg, *colptr, *cursor;
    bf16* bfb;
    cudaGetSymbolAddress((void**)&hf,     g_h);
    cudaGetSymbolAddress((void**)&tf,     g_tmp);
    cudaGetSymbolAddress((void**)&t1f,    g_t1f);
    cudaGetSymbolAddress((void**)&stats,  g_stats);
    cudaGetSymbolAddress((void**)&deg,    g_deg);
    cudaGetSymbolAddress((void**)&colptr, g_colptr);
    cudaGetSymbolAddress((void**)&cursor, g_cursor);
    cudaGetSymbolAddress((void**)&bfb,    g_bf);

    bf16 *hsH = bfb + OFF_HSA_H, *hsL = bfb + OFF_HSA_L;
    bf16 *tsH = bfb + OFF_HSB_H, *tsL = bfb + OFF_HSB_L;
    bf16 *agH = bfb + OFF_AGG_H, *agL = bfb + OFF_AGG_L;
    bf16 *xH  = bfb + OFF_X_H,   *xL  = bfb + OFF_X_L;
    bf16 *t1H = bfb + OFF_T1_H,  *t1L = bfb + OFF_T1_L;
    bf16 *WinH = bfb + OFF_WIN_H, *WinL = bfb + OFF_WIN_L;
    bf16 *WlH  = bfb + OFF_WL_H,  *WlL  = bfb + OFF_WL_L;
    bf16 *WrH  = bfb + OFF_WR_H,  *WrL  = bfb + OFF_WR_L;
    bf16 *WskH = bfb + OFF_WSK_H, *WskL = bfb + OFF_WSK_L;
    bf16 *W1H  = bfb + OFF_W1_H,  *W1L  = bfb + OFF_W1_L;
    bf16 *W2H  = bfb + OFF_W2_H,  *W2L  = bfb + OFF_W2_L;

    const int* e_row = ei;
    const int* e_col = ei + N_EDGES;

    // ---- CSR build ----
    cudaMemsetAsync(deg, 0, N_NODES * sizeof(int));
    hist_kernel<<<(N_EDGES + 255) / 256, 256>>>(e_col);
    scan_kernel<<<1, 1024>>>();
    cudaMemcpyAsync(cursor, colptr, N_NODES * sizeof(int), cudaMemcpyDeviceToDevice);
    fill_kernel<<<(N_EDGES + 255) / 256, 256>>>(e_row, e_col);
    invcnt_kernel<<<(N_NODES + 255) / 256, 256>>>();

    // ---- split weights + x ----
    run_split(W_in,  WinH, WinL, SZ_WIN);
    run_split(Wl,    WlH,  WlL,  SZ_WL);
    run_split(Wr,    WrH,  WrL,  SZ_WL);
    run_split(Wskip, WskH, WskL, SZ_WSK);
    run_split(W1,    W1H,  W1L,  SZ_W1);
    run_split(W2,    W2H,  W2L,  SZ_W2);
    run_split(x,     xH,   xL,   (size_t)N_NODES * DIN);

    // ---- input layer: h = relu(bn0(x @ W_in + b_in)); stats fused into epilogue ----
    cudaMemsetAsync(stats, 0, 2 * H * sizeof(float));   // once; bn_final re-zeroes
    run_gemm(xH, xL, WinH, WinL, DIN,
             nullptr, nullptr, nullptr, nullptr, 0,
             b_in, hf, hf, nullptr, nullptr, N_NODES, H, /*bias|stats*/9);
    bn_final_kernel<<<1, H>>>(bn0_g, bn0_b);
    {
        int total4 = N_NODES * H / 4;
        bn_apply_relu_kernel<<<(total4 + 255) / 256, 256>>>(hf, hsH, hsL);
    }

    // ---- SAGE layers ----
    int skip = 0;
    for (int i = 0; i < NLAYERS; i++) {
        bool is_skip = ((i & 1) == 1);
        agg_kernel<<<(N_NODES * 32 + 255) / 256, 256>>>(hf, agH, agL);
        // tmp = agg@Wl + bl + h@Wr (raw); col stats fused
        run_gemm(agH, agL, WlH + (size_t)i * H * H, WlL + (size_t)i * H * H, H,
                 hsH, hsL, WrH + (size_t)i * H * H, WrL + (size_t)i * H * H, H,
                 bl + (size_t)i * H, tf, tf, nullptr, nullptr, N_NODES, H, /*bias|stats*/9);
        bn_final_kernel<<<1, H>>>(bn_g + (size_t)i * H, bn_b + (size_t)i * H);
        if (is_skip) {
            // out = relu(bn(tf)) + identity@Wskip + bskip  (BN fused into skip epilogue)
            float* outp = (i == NLAYERS - 1) ? emb_out : tf;
            run_gemm(hsH, hsL, WskH + (size_t)skip * H * H, WskL + (size_t)skip * H * H, H,
                     nullptr, nullptr, nullptr, nullptr, 0,
                     bskip + (size_t)skip * H, tf, outp, tsH, tsL,
                     N_NODES, H, /*bias|skipBN*/17);
            skip++;
            if (i == NLAYERS - 1) {
                bf16* bt;
                bt = hsH; hsH = tsH; tsH = bt;
                bt = hsL; hsL = tsL; tsL = bt;
                break;
            }
        } else {
            int total4 = N_NODES * H / 4;
            bn_apply_relu_kernel<<<(total4 + 255) / 256, 256>>>(tf, tsH, tsL);
        }
        float* ft = hf; hf = tf; tf = ft;
        bf16* bt;
        bt = hsH; hsH = tsH; tsH = bt;
        bt = hsL; hsL = tsL; tsL = bt;
    }

    // ---- MLP head (embeddings already written to emb_out by last skip GEMM) ----
    run_gemm(hsH, hsL, W1H, W1L, H,
             nullptr, nullptr, nullptr, nullptr, 0,
             b1, t1f, t1f, t1H, t1L, N_NODES, H / 2, /*bias|relu*/5);
    run_gemm(t1H, t1L, W2H, W2L, H / 2,
             nullptr, nullptr, nullptr, nullptr, 0,
             b2, tf, tf, nullptr, nullptr, N_NODES, H / 4, /*bias|relu*/5);
    head3_kernel<<<(N_NODES + 255) / 256, 256>>>(tf, W3, b3, logits_out);
}

// round 16
// speedup vs baseline: 1.1062x; 1.1062x over previous
#include <cuda_runtime.h>
#include <cuda_bf16.h>
#include <math.h>
#include <stdint.h>

#define N_NODES 50000
#define N_EDGES 800000
#define DIN     256
#define H       384
#define NLAYERS 6
#define NCLS    2
#define EPSV    1e-5f

typedef __nv_bfloat16 bf16;

// ---------------- fp32 scratch ----------------
__device__ float g_h   [(size_t)N_NODES * H];
__device__ float g_tmp [(size_t)N_NODES * H];
__device__ float g_t1f [(size_t)N_NODES * H];
__device__ float g_stats[2 * H];
__device__ float g_bna [H];
__device__ float g_bnc [H];
__device__ float g_invcnt[N_NODES];
__device__ int   g_deg   [N_NODES];
__device__ int   g_colptr[N_NODES + 1];
__device__ int   g_cursor[N_NODES];
__device__ int   g_src   [N_EDGES];

// ---------------- bf16 split scratch ----------------
#define NH ((size_t)N_NODES * H)
static const size_t OFF_HSA_H = 0;
static const size_t OFF_HSA_L = 1 * NH;
static const size_t OFF_HSB_H = 2 * NH;
static const size_t OFF_HSB_L = 3 * NH;
static const size_t OFF_AGG_H = 4 * NH;
static const size_t OFF_AGG_L = 5 * NH;
static const size_t OFF_X_H   = 6 * NH;
static const size_t OFF_X_L   = 7 * NH;
static const size_t OFF_T1_H  = 8 * NH;
static const size_t OFF_T1_L  = 9 * NH;
static const size_t SZ_WIN = (size_t)DIN * H;
static const size_t SZ_WL  = (size_t)NLAYERS * H * H;
static const size_t SZ_WSK = (size_t)(NLAYERS / 2) * H * H;
static const size_t SZ_W1  = (size_t)H * (H / 2);
static const size_t SZ_W2  = (size_t)(H / 2) * (H / 4);
static const size_t OFF_WIN_H = 10 * NH;
static const size_t OFF_WIN_L = OFF_WIN_H + SZ_WIN;
static const size_t OFF_WL_H  = OFF_WIN_L + SZ_WIN;
static const size_t OFF_WL_L  = OFF_WL_H + SZ_WL;
static const size_t OFF_WR_H  = OFF_WL_L + SZ_WL;
static const size_t OFF_WR_L  = OFF_WR_H + SZ_WL;
static const size_t OFF_WSK_H = OFF_WR_L + SZ_WL;
static const size_t OFF_WSK_L = OFF_WSK_H + SZ_WSK;
static const size_t OFF_W1_H  = OFF_WSK_L + SZ_WSK;
static const size_t OFF_W1_L  = OFF_W1_H + SZ_W1;
static const size_t OFF_W2_H  = OFF_W1_L + SZ_W1;
static const size_t OFF_W2_L  = OFF_W2_H + SZ_W2;
static const size_t BF_TOTAL  = OFF_W2_L + SZ_W2;

__device__ bf16 g_bf[BF_TOTAL];

// ---------------- CSR build ----------------
__global__ void hist_kernel(const int* __restrict__ col) {
    int i = blockIdx.x * blockDim.x + threadIdx.x;
    if (i < N_EDGES) atomicAdd(&g_deg[col[i]], 1);
}

__global__ void scan_kernel() {
    __shared__ int buf[1024];
    int tid = threadIdx.x;
    int offset = 0;
    for (int base = 0; base < N_NODES; base += 1024) {
        int idx = base + tid;
        int v = (idx < N_NODES) ? g_deg[idx] : 0;
        buf[tid] = v;
        __syncthreads();
        for (int s = 1; s < 1024; s <<= 1) {
            int t = (tid >= s) ? buf[tid - s] : 0;
            __syncthreads();
            buf[tid] += t;
            __syncthreads();
        }
        if (idx < N_NODES) g_colptr[idx] = offset + buf[tid] - v;
        int tot = buf[1023];
        __syncthreads();
        offset += tot;
    }
    if (tid == 0) g_colptr[N_NODES] = offset;
}

__global__ void fill_kernel(const int* __restrict__ row, const int* __restrict__ col) {
    int i = blockIdx.x * blockDim.x + threadIdx.x;
    if (i < N_EDGES) {
        int p = atomicAdd(&g_cursor[col[i]], 1);
        g_src[p] = row[i];
    }
}

__global__ void invcnt_kernel() {
    int i = blockIdx.x * blockDim.x + threadIdx.x;
    if (i < N_NODES) g_invcnt[i] = 1.0f / fmaxf((float)g_deg[i], 1.0f);
}

// ---------------- splits ----------------
__global__ void split_kernel(const float* __restrict__ src,
                             bf16* __restrict__ hi, bf16* __restrict__ lo, int n) {
    int i = blockIdx.x * blockDim.x + threadIdx.x;
    if (i < n) {
        float v = src[i];
        bf16 h = __float2bfloat16(v);
        hi[i] = h;
        lo[i] = __float2bfloat16(v - __bfloat162float(h));
    }
}

// ---------------- mean aggregation (R11-proven simple loop) ----------------
__global__ void agg_kernel(const float* __restrict__ h,
                           bf16* __restrict__ ohi, bf16* __restrict__ olo) {
    int w    = (blockIdx.x * blockDim.x + threadIdx.x) >> 5;
    int lane = threadIdx.x & 31;
    if (w >= N_NODES) return;
    int beg = g_colptr[w], end = g_colptr[w + 1];
    float4 a0 = make_float4(0.f, 0.f, 0.f, 0.f);
    float4 a1 = a0, a2 = a0;
    for (int e = beg; e < end; e++) {
        const float4* hp = (const float4*)(h + (size_t)g_src[e] * H);
        float4 v0 = hp[lane];
        float4 v1 = hp[lane + 32];
        float4 v2 = hp[lane + 64];
        a0.x += v0.x; a0.y += v0.y; a0.z += v0.z; a0.w += v0.w;
        a1.x += v1.x; a1.y += v1.y; a1.z += v1.z; a1.w += v1.w;
        a2.x += v2.x; a2.y += v2.y; a2.z += v2.z; a2.w += v2.w;
    }
    float s = g_invcnt[w];
    float vals[12] = {a0.x*s, a0.y*s, a0.z*s, a0.w*s,
                      a1.x*s, a1.y*s, a1.z*s, a1.w*s,
                      a2.x*s, a2.y*s, a2.z*s, a2.w*s};
    size_t base = (size_t)w * H + lane * 4;
#pragma unroll
    for (int g = 0; g < 3; g++) {
#pragma unroll
        for (int j = 0; j < 4; j++) {
            float v = vals[g * 4 + j];
            bf16 hb = __float2bfloat16(v);
            ohi[base + g * 128 + j] = hb;
            olo[base + g * 128 + j] = __float2bfloat16(v - __bfloat162float(hb));
        }
    }
}

// ---------------- mma helpers ----------------
__device__ __forceinline__ void ldsm_x4(uint32_t* r, const void* p) {
    uint32_t a = (uint32_t)__cvta_generic_to_shared(p);
    asm volatile("ldmatrix.sync.aligned.m8n8.x4.shared.b16 {%0,%1,%2,%3}, [%4];"
                 : "=r"(r[0]), "=r"(r[1]), "=r"(r[2]), "=r"(r[3]) : "r"(a));
}
__device__ __forceinline__ void ldsm_x4t(uint32_t* r, const void* p) {
    uint32_t a = (uint32_t)__cvta_generic_to_shared(p);
    asm volatile("ldmatrix.sync.aligned.m8n8.x4.trans.shared.b16 {%0,%1,%2,%3}, [%4];"
                 : "=r"(r[0]), "=r"(r[1]), "=r"(r[2]), "=r"(r[3]) : "r"(a));
}
__device__ __forceinline__ void mma16816(float* d, const uint32_t* a, const uint32_t* b) {
    asm volatile("mma.sync.aligned.m16n8k16.row.col.f32.bf16.bf16.f32 "
                 "{%0,%1,%2,%3}, {%4,%5,%6,%7}, {%8,%9}, {%0,%1,%2,%3};"
                 : "+f"(d[0]), "+f"(d[1]), "+f"(d[2]), "+f"(d[3])
                 : "r"(a[0]), "r"(a[1]), "r"(a[2]), "r"(a[3]), "r"(b[0]), "r"(b[1]));
}
__device__ __forceinline__ void cpasync16(void* dst, const void* src, bool pred) {
    uint32_t d = (uint32_t)__cvta_generic_to_shared(dst);
    int sz = pred ? 16 : 0;
    asm volatile("cp.async.cg.shared.global [%0], [%1], 16, %2;"
                 :: "r"(d), "l"(src), "r"(sz) : "memory");
}
#define CP_COMMIT() asm volatile("cp.async.commit_group;" ::: "memory")
#define CP_WAIT0()  asm volatile("cp.async.wait_group 0;" ::: "memory")

// ---------------- bf16x3 tensor-core GEMM, 2-stage, ONE sync per chunk ----------------
// flags: 1=+bias, 2=acc C, 4=relu, 8=fused BN col-stats, 16=skip-BN (v = relu(bn(Cin)) + acc + bias)
static const int A_PITCH = 40;
static const int B_PITCH = 136;
static const int A_ELEMS = 128 * A_PITCH;
static const int B_ELEMS = 32 * B_PITCH;
static const int STAGE_ELEMS = 2 * A_ELEMS + 2 * B_ELEMS;   // 18944 bf16 = 37888 B
static const int SMEM_DYN = 2 * STAGE_ELEMS * 2;            // 75776 B

__global__ void __launch_bounds__(256) gemm_mma_kernel(
    const bf16* __restrict__ a1h, const bf16* __restrict__ a1l,
    const bf16* __restrict__ b1h, const bf16* __restrict__ b1l, int K1,
    const bf16* __restrict__ a2h, const bf16* __restrict__ a2l,
    const bf16* __restrict__ b2h, const bf16* __restrict__ b2l, int K2,
    const float* __restrict__ bias,
    const float* __restrict__ Cin, float* __restrict__ Cout,
    bf16* __restrict__ ohi, bf16* __restrict__ olo,
    int M, int Nc, int flags)
{
    extern __shared__ bf16 sm[];

    const int tid  = threadIdx.x;
    const int lane = tid & 31;
    const int wid  = tid >> 5;
    const int wm   = (wid >> 2) * 64;
    const int wn   = (wid & 3) * 32;
    const int m0   = blockIdx.y * 128;
    const int n0   = blockIdx.x * 128;

    const int nch1 = K1 >> 5;
    const int nch2 = (a2h != nullptr) ? (K2 >> 5) : 0;
    const int NCH  = nch1 + nch2;

    float acc[4][4][4];
#pragma unroll
    for (int i = 0; i < 4; i++)
#pragma unroll
        for (int j = 0; j < 4; j++)
#pragma unroll
            for (int k = 0; k < 4; k++) acc[i][j][k] = 0.f;

    auto load_stage = [&](int buf, int c) {
        const bf16 *ah, *al, *bh, *bl; int K, kk;
        if (c < nch1) { ah = a1h; al = a1l; bh = b1h; bl = b1l; K = K1; kk = c * 32; }
        else          { ah = a2h; al = a2l; bh = b2h; bl = b2l; K = K2; kk = (c - nch1) * 32; }
        bf16* AhS = sm + buf * STAGE_ELEMS;
        bf16* AlS = AhS + A_ELEMS;
        bf16* BhS = AlS + A_ELEMS;
        bf16* BlS = BhS + B_ELEMS;
#pragma unroll
        for (int t = 0; t < 2; t++) {
            int idx = tid + t * 256;
            int row = idx >> 2, cg = idx & 3;
            int gr = m0 + row;
            bool ok = gr < M;
            size_t so = (size_t)gr * K + kk + cg * 8;
            int doff = row * A_PITCH + cg * 8;
            cpasync16(AhS + doff, ah + (ok ? so : 0), ok);
            cpasync16(AlS + doff, al + (ok ? so : 0), ok);
        }
#pragma unroll
        for (int t = 0; t < 2; t++) {
            int idx = tid + t * 256;
            int row = idx >> 4, cg = idx & 15;
            int gc = n0 + cg * 8;
            bool ok = gc < Nc;
            size_t so = (size_t)(kk + row) * Nc + (ok ? gc : 0);
            int doff = row * B_PITCH + cg * 8;
            cpasync16(BhS + doff, bh + so, ok);
            cpasync16(BlS + doff, bl + so, ok);
        }
    };

    auto compute_stage = [&](int buf) {
        const bf16* AhS = sm + buf * STAGE_ELEMS;
        const bf16* AlS = AhS + A_ELEMS;
        const bf16* BhS = AlS + A_ELEMS;
#pragma unroll
        for (int ks = 0; ks < 2; ks++) {
            uint32_t bfh[8], bfl[8], af[4][4];
#pragma unroll
            for (int ni2 = 0; ni2 < 2; ni2++) {
                const bf16* bb = BhS + (ks * 16 + (lane & 15)) * B_PITCH
                                     + wn + ni2 * 16 + ((lane >> 4) << 3);
                ldsm_x4t(&bfh[ni2 * 4], bb);
                ldsm_x4t(&bfl[ni2 * 4], bb + B_ELEMS);
            }
#pragma unroll
            for (int mi = 0; mi < 4; mi++)
                ldsm_x4(af[mi], AhS + (wm + mi * 16 + (lane & 15)) * A_PITCH
                                   + ks * 16 + (lane >> 4) * 8);
#pragma unroll
            for (int mi = 0; mi < 4; mi++)
#pragma unroll
                for (int ni = 0; ni < 4; ni++)
                    mma16816(acc[mi][ni], af[mi], &bfh[ni * 2]);
#pragma unroll
            for (int mi = 0; mi < 4; mi++)
#pragma unroll
                for (int ni = 0; ni < 4; ni++)
                    mma16816(acc[mi][ni], af[mi], &bfl[ni * 2]);
#pragma unroll
            for (int mi = 0; mi < 4; mi++)
                ldsm_x4(af[mi], AlS + (wm + mi * 16 + (lane & 15)) * A_PITCH
                                   + ks * 16 + (lane >> 4) * 8);
#pragma unroll
            for (int mi = 0; mi < 4; mi++)
#pragma unroll
                for (int ni = 0; ni < 4; ni++)
                    mma16816(acc[mi][ni], af[mi], &bfh[ni * 2]);
        }
    };

    // ---- 2-stage double buffer, ONE sync per chunk ----
    // Order per iter: wait(group c) -> sync -> issue load(c+1) -> compute(c).
    // The single sync proves (a) chunk-c data visible and (b) every warp finished
    // compute(c-1), so load(c+1) overwriting buffer (c+1)&1 is safe.
    load_stage(0, 0);
    CP_COMMIT();
    for (int c = 0; c < NCH; c++) {
        CP_WAIT0();                 // only group c is outstanding here
        __syncthreads();
        if (c + 1 < NCH) { load_stage((c + 1) & 1, c + 1); CP_COMMIT(); }
        compute_stage(c & 1);
    }
    __syncthreads();                // all compute done before smem reuse below

    // ---- epilogue ----
    float* scol = (float*)sm;
    const bool do_stats = (flags & 8) != 0;
    if (do_stats) {
        if (tid < 256) scol[tid] = 0.f;
        __syncthreads();
    }

    float ls[4][2], ls2[4][2];
    if (do_stats) {
#pragma unroll
        for (int ni = 0; ni < 4; ni++) { ls[ni][0]=ls[ni][1]=ls2[ni][0]=ls2[ni][1]=0.f; }
    }

#pragma unroll
    for (int mi = 0; mi < 4; mi++) {
#pragma unroll
        for (int ni = 0; ni < 4; ni++) {
            int rbase = m0 + wm + mi * 16 + (lane >> 2);
            int cbase = n0 + wn + ni * 8 + (lane & 3) * 2;
#pragma unroll
            for (int half = 0; half < 2; half++) {
                int r = rbase + half * 8;
                if (r < M) {
#pragma unroll
                    for (int j = 0; j < 2; j++) {
                        int c = cbase + j;
                        if (c < Nc) {
                            float v = acc[mi][ni][half * 2 + j];
                            if (flags & 1) v += bias[c];
                            if (flags & 2) v += Cin[(size_t)r * Nc + c];
                            if (flags & 16) {
                                float old = Cin[(size_t)r * Nc + c];
                                v += fmaxf(fmaf(old, g_bna[c], g_bnc[c]), 0.f);
                            }
                            if (flags & 4) v = fmaxf(v, 0.f);
                            Cout[(size_t)r * Nc + c] = v;
                            if (do_stats) {
                                ls [ni][j] += v;
                                ls2[ni][j] = fmaf(v, v, ls2[ni][j]);
                            }
                            if (ohi) {
                                bf16 hv = __float2bfloat16(v);
                                ohi[(size_t)r * Nc + c] = hv;
                                olo[(size_t)r * Nc + c] =
                                    __float2bfloat16(v - __bfloat162float(hv));
                            }
                        }
                    }
                }
            }
        }
    }

    if (do_stats) {
#pragma unroll
        for (int ni = 0; ni < 4; ni++) {
#pragma unroll
            for (int j = 0; j < 2; j++) {
                int cloc = wn + ni * 8 + (lane & 3) * 2 + j;
                atomicAdd(&scol[cloc], ls[ni][j]);
                atomicAdd(&scol[128 + cloc], ls2[ni][j]);
            }
        }
        __syncthreads();
        if (tid < 128) {
            int c = n0 + tid;
            if (c < Nc) {
                atomicAdd(&g_stats[c],     scol[tid]);
                atomicAdd(&g_stats[H + c], scol[128 + tid]);
            }
        }
    }
}

// ---------------- batchnorm ----------------
__global__ void bn_final_kernel(const float* __restrict__ g, const float* __restrict__ b) {
    int c = threadIdx.x;
    if (c < H) {
        float inv = 1.0f / (float)N_NODES;
        float mu  = g_stats[c] * inv;
        float var = g_stats[H + c] * inv - mu * mu;
        float rs  = rsqrtf(var + EPSV);
        float a   = g[c] * rs;
        g_bna[c] = a;
        g_bnc[c] = b[c] - mu * a;
        g_stats[c]     = 0.f;
        g_stats[H + c] = 0.f;
    }
}

__global__ void bn_apply_relu_kernel(float* __restrict__ h,
                                     bf16* __restrict__ ohi, bf16* __restrict__ olo) {
    int i = blockIdx.x * blockDim.x + threadIdx.x;
    const int total = N_NODES * H / 4;
    if (i >= total) return;
    int c4 = i % (H / 4);
    float4 v = ((float4*)h)[i];
    float4 a = ((const float4*)g_bna)[c4];
    float4 c = ((const float4*)g_bnc)[c4];
    v.x = fmaxf(fmaf(v.x, a.x, c.x), 0.f);
    v.y = fmaxf(fmaf(v.y, a.y, c.y), 0.f);
    v.z = fmaxf(fmaf(v.z, a.z, c.z), 0.f);
    v.w = fmaxf(fmaf(v.w, a.w, c.w), 0.f);
    ((float4*)h)[i] = v;
    if (ohi) {
        size_t base = (size_t)i * 4;
        float vv[4] = {v.x, v.y, v.z, v.w};
        bf16 hb[4], lb[4];
#pragma unroll
        for (int j = 0; j < 4; j++) {
            hb[j] = __float2bfloat16(vv[j]);
            lb[j] = __float2bfloat16(vv[j] - __bfloat162float(hb[j]));
        }
        ((__nv_bfloat162*)(ohi + base))[0] = __halves2bfloat162(hb[0], hb[1]);
        ((__nv_bfloat162*)(ohi + base))[1] = __halves2bfloat162(hb[2], hb[3]);
        ((__nv_bfloat162*)(olo + base))[0] = __halves2bfloat162(lb[0], lb[1]);
        ((__nv_bfloat162*)(olo + base))[1] = __halves2bfloat162(lb[2], lb[3]);
    }
}

// ---------------- final tiny GEMM ----------------
__global__ void head3_kernel(const float* __restrict__ t2, const float* __restrict__ W3,
                             const float* __restrict__ b3, float* __restrict__ out) {
    __shared__ float w[96 * 2];
    __shared__ float bb[2];
    if (threadIdx.x < 192) w[threadIdx.x] = W3[threadIdx.x];
    if (threadIdx.x < 2)   bb[threadIdx.x] = b3[threadIdx.x];
    __syncthreads();
    int r = blockIdx.x * blockDim.x + threadIdx.x;
    if (r >= N_NODES) return;
    float a0 = bb[0], a1 = bb[1];
    const float* row = t2 + (size_t)r * 96;
#pragma unroll 8
    for (int k = 0; k < 96; k++) {
        float v = row[k];
        a0 = fmaf(v, w[k * 2],     a0);
        a1 = fmaf(v, w[k * 2 + 1], a1);
    }
    out[r * 2]     = a0;
    out[r * 2 + 1] = a1;
}

// ---------------- host orchestration ----------------
static void run_split(const float* src, bf16* hi, bf16* lo, size_t n) {
    split_kernel<<<(int)((n + 255) / 256), 256>>>(src, hi, lo, (int)n);
}

static void run_gemm(const bf16* a1h, const bf16* a1l, const bf16* b1h, const bf16* b1l, int K1,
                     const bf16* a2h, const bf16* a2l, const bf16* b2h, const bf16* b2l, int K2,
                     const float* bias, const float* Cin, float* Cout, bf16* ohi, bf16* olo,
                     int M, int Nc, int flags) {
    static int attr_set = 0;
    if (!attr_set) {
        cudaFuncSetAttribute(gemm_mma_kernel,
                             cudaFuncAttributeMaxDynamicSharedMemorySize, SMEM_DYN);
        attr_set = 1;
    }
    dim3 grid((Nc + 127) / 128, (M + 127) / 128);
    gemm_mma_kernel<<<grid, 256, SMEM_DYN>>>(a1h, a1l, b1h, b1l, K1,
                                             a2h, a2l, b2h, b2l, K2,
                                             bias, Cin, Cout, ohi, olo, M, Nc, flags);
}

extern "C" void kernel_launch(void* const* d_in, const int* in_sizes, int n_in,
                              void* d_out, int out_size) {
    const float* x     = (const float*)d_in[0];
    const int*   ei    = (const int*)  d_in[1];
    const float* W_in  = (const float*)d_in[2];
    const float* b_in  = (const float*)d_in[3];
    const float* bn0_g = (const float*)d_in[4];
    const float* bn0_b = (const float*)d_in[5];
    const float* Wl    = (const float*)d_in[6];
    const float* bl    = (const float*)d_in[7];
    const float* Wr    = (const float*)d_in[8];
    const float* bn_g  = (const float*)d_in[9];
    const float* bn_b  = (const float*)d_in[10];
    const float* Wskip = (const float*)d_in[11];
    const float* bskip = (const float*)d_in[12];
    const float* W1    = (const float*)d_in[13];
    const float* b1    = (const float*)d_in[14];
    const float* W2    = (const float*)d_in[15];
    const float* b2    = (const float*)d_in[16];
    const float* W3    = (const float*)d_in[17];
    const float* b3    = (const float*)d_in[18];

    float* logits_out = (float*)d_out;
    float* emb_out    = logits_out + (size_t)N_NODES * NCLS;

    float *hf, *tf, *t1f, *stats;
    int *deg, *colptr, *cursor;
    bf16* bfb;
    cudaGetSymbolAddress((void**)&hf,     g_h);
    cudaGetSymbolAddress((void**)&tf,     g_tmp);
    cudaGetSymbolAddress((void**)&t1f,    g_t1f);
    cudaGetSymbolAddress((void**)&stats,  g_stats);
    cudaGetSymbolAddress((void**)&deg,    g_deg);
    cudaGetSymbolAddress((void**)&colptr, g_colptr);
    cudaGetSymbolAddress((void**)&cursor, g_cursor);
    cudaGetSymbolAddress((void**)&bfb,    g_bf);

    bf16 *hsH = bfb + OFF_HSA_H, *hsL = bfb + OFF_HSA_L;
    bf16 *tsH = bfb + OFF_HSB_H, *tsL = bfb + OFF_HSB_L;
    bf16 *agH = bfb + OFF_AGG_H, *agL = bfb + OFF_AGG_L;
    bf16 *xH  = bfb + OFF_X_H,   *xL  = bfb + OFF_X_L;
    bf16 *t1H = bfb + OFF_T1_H,  *t1L = bfb + OFF_T1_L;
    bf16 *WinH = bfb + OFF_WIN_H, *WinL = bfb + OFF_WIN_L;
    bf16 *WlH  = bfb + OFF_WL_H,  *WlL  = bfb + OFF_WL_L;
    bf16 *WrH  = bfb + OFF_WR_H,  *WrL  = bfb + OFF_WR_L;
    bf16 *WskH = bfb + OFF_WSK_H, *WskL = bfb + OFF_WSK_L;
    bf16 *W1H  = bfb + OFF_W1_H,  *W1L  = bfb + OFF_W1_L;
    bf16 *W2H  = bfb + OFF_W2_H,  *W2L  = bfb + OFF_W2_L;

    const int* e_row = ei;
    const int* e_col = ei + N_EDGES;

    // ---- CSR build ----
    cudaMemsetAsync(deg, 0, N_NODES * sizeof(int));
    hist_kernel<<<(N_EDGES + 255) / 256, 256>>>(e_col);
    scan_kernel<<<1, 1024>>>();
    cudaMemcpyAsync(cursor, colptr, N_NODES * sizeof(int), cudaMemcpyDeviceToDevice);
    fill_kernel<<<(N_EDGES + 255) / 256, 256>>>(e_row, e_col);
    invcnt_kernel<<<(N_NODES + 255) / 256, 256>>>();

    // ---- split weights + x ----
    run_split(W_in,  WinH, WinL, SZ_WIN);
    run_split(Wl,    WlH,  WlL,  SZ_WL);
    run_split(Wr,    WrH,  WrL,  SZ_WL);
    run_split(Wskip, WskH, WskL, SZ_WSK);
    run_split(W1,    W1H,  W1L,  SZ_W1);
    run_split(W2,    W2H,  W2L,  SZ_W2);
    run_split(x,     xH,   xL,   (size_t)N_NODES * DIN);

    // ---- input layer: h = relu(bn0(x @ W_in + b_in)); stats fused into epilogue ----
    cudaMemsetAsync(stats, 0, 2 * H * sizeof(float));   // once; bn_final re-zeroes
    run_gemm(xH, xL, WinH, WinL, DIN,
             nullptr, nullptr, nullptr, nullptr, 0,
             b_in, hf, hf, nullptr, nullptr, N_NODES, H, /*bias|stats*/9);
    bn_final_kernel<<<1, H>>>(bn0_g, bn0_b);
    {
        int total4 = N_NODES * H / 4;
        bn_apply_relu_kernel<<<(total4 + 255) / 256, 256>>>(hf, hsH, hsL);
    }

    // ---- SAGE layers ----
    int skip = 0;
    for (int i = 0; i < NLAYERS; i++) {
        bool is_skip = ((i & 1) == 1);
        agg_kernel<<<(N_NODES * 32 + 255) / 256, 256>>>(hf, agH, agL);
        // tmp = agg@Wl + bl + h@Wr (raw); col stats fused
        run_gemm(agH, agL, WlH + (size_t)i * H * H, WlL + (size_t)i * H * H, H,
                 hsH, hsL, WrH + (size_t)i * H * H, WrL + (size_t)i * H * H, H,
                 bl + (size_t)i * H, tf, tf, nullptr, nullptr, N_NODES, H, /*bias|stats*/9);
        bn_final_kernel<<<1, H>>>(bn_g + (size_t)i * H, bn_b + (size_t)i * H);
        if (is_skip) {
            // out = relu(bn(tf)) + identity@Wskip + bskip  (BN fused into skip epilogue)
            float* outp = (i == NLAYERS - 1) ? emb_out : tf;
            run_gemm(hsH, hsL, WskH + (size_t)skip * H * H, WskL + (size_t)skip * H * H, H,
                     nullptr, nullptr, nullptr, nullptr, 0,
                     bskip + (size_t)skip * H, tf, outp, tsH, tsL,
                     N_NODES, H, /*bias|skipBN*/17);
            skip++;
            if (i == NLAYERS - 1) {
                bf16* bt;
                bt = hsH; hsH = tsH; tsH = bt;
                bt = hsL; hsL = tsL; tsL = bt;
                break;
            }
        } else {
            int total4 = N_NODES * H / 4;
            bn_apply_relu_kernel<<<(total4 + 255) / 256, 256>>>(tf, tsH, tsL);
        }
        float* ft = hf; hf = tf; tf = ft;
        bf16* bt;
        bt = hsH; hsH = tsH; tsH = bt;
        bt = hsL; hsL = tsL; tsL = bt;
    }

    // ---- MLP head (embeddings already written to emb_out by last skip GEMM) ----
    run_gemm(hsH, hsL, W1H, W1L, H,
             nullptr, nullptr, nullptr, nullptr, 0,
             b1, t1f, t1f, t1H, t1L, N_NODES, H / 2, /*bias|relu*/5);
    run_gemm(t1H, t1L, W2H, W2L, H / 2,
             nullptr, nullptr, nullptr, nullptr, 0,
             b2, tf, tf, nullptr, nullptr, N_NODES, H / 4, /*bias|relu*/5);
    head3_kernel<<<(N_NODES + 255) / 256, 256>>>(tf, W3, b3, logits_out);
}